// round 1
// baseline (speedup 1.0000x reference)
#include <cuda_runtime.h>
#include <math.h>

#define MTOK 65536   // 8 * 8192 tokens
#define D    128
#define HDIM 256

// ---------------- scratch (device globals: no allocation allowed) ----------
__device__ float g_xn [(size_t)MTOK * D];      // LayerNorm'd mixing output
__device__ float g_hid[(size_t)MTOK * HDIM];   // GELU(xn @ W1 + b1)
__device__ float g_blk[4][(size_t)MTOK * D];   // committed blocks / running partial

struct SrcPtrs { const float* p[5]; };

__device__ __forceinline__ float wsum(float v) {
#pragma unroll
    for (int o = 16; o > 0; o >>= 1) v += __shfl_xor_sync(0xffffffffu, v, o);
    return v;
}

// ---------------- mixing kernel: rmsnorm-dot -> softmax -> mix (-> LN) -----
// One warp per token. Sources kept in registers (n <= 5).
// WRITE_H=true  : write mixed h (final layer, straight to d_out)
// WRITE_H=false : fuse LayerNorm(affine) and write xn
template<bool WRITE_H>
__global__ __launch_bounds__(256)
void mix_kernel(SrcPtrs src, int n, const float* __restrict__ wrow,
                const float* __restrict__ lg, const float* __restrict__ lb,
                float* __restrict__ outp) {
    int tok  = (blockIdx.x * 256 + threadIdx.x) >> 5;
    int lane = threadIdx.x & 31;
    int base = tok * D + lane * 4;

    float4 wv = *(const float4*)(wrow + lane * 4);

    float4 v[5];
    float  lgt[5];
#pragma unroll
    for (int i = 0; i < 5; i++) {
        if (i < n) {
            float4 t = *(const float4*)(src.p[i] + base);
            v[i] = t;
            float ss = t.x*t.x + t.y*t.y + t.z*t.z + t.w*t.w;
            float dt = wv.x*t.x + wv.y*t.y + wv.z*t.z + wv.w*t.w;
            ss = wsum(ss);
            dt = wsum(dt);
            lgt[i] = dt * rsqrtf(ss * (1.0f / D) + 1e-8f);
        }
    }

    float mx = -1e30f;
#pragma unroll
    for (int i = 0; i < 5; i++) if (i < n) mx = fmaxf(mx, lgt[i]);
    float se = 0.f;
#pragma unroll
    for (int i = 0; i < 5; i++) if (i < n) { lgt[i] = expf(lgt[i] - mx); se += lgt[i]; }
    float inv = 1.f / se;

    float hx = 0.f, hy = 0.f, hz = 0.f, hw = 0.f;
#pragma unroll
    for (int i = 0; i < 5; i++) if (i < n) {
        float wt = lgt[i] * inv;
        hx += wt * v[i].x; hy += wt * v[i].y; hz += wt * v[i].z; hw += wt * v[i].w;
    }

    if (WRITE_H) {
        float4 o = {hx, hy, hz, hw};
        *(float4*)(outp + base) = o;
    } else {
        float mu = wsum(hx + hy + hz + hw) * (1.0f / D);
        float dx = hx - mu, dy = hy - mu, dz = hz - mu, dw = hw - mu;
        float var = wsum(dx*dx + dy*dy + dz*dz + dw*dw) * (1.0f / D);
        float r = rsqrtf(var + 1e-5f);
        float4 gg = *(const float4*)(lg + lane * 4);
        float4 bb = *(const float4*)(lb + lane * 4);
        float4 o;
        o.x = dx * r * gg.x + bb.x;
        o.y = dy * r * gg.y + bb.y;
        o.z = dz * r * gg.z + bb.z;
        o.w = dw * r * gg.w + bb.w;
        *(float4*)(outp + base) = o;
    }
}

// ---------------- fp32 SGEMM 128x128x8, 8x8 per thread ---------------------
// C[M,N] = epilogue(A[M,K] @ B[K,N] + bias[N])
// DO_GELU: exact gelu on result; DO_ACC: C += result (partial accumulation)
template<bool DO_GELU, bool DO_ACC>
__global__ __launch_bounds__(256, 2)
void gemm_kernel(const float* __restrict__ A, const float* __restrict__ B,
                 const float* __restrict__ bias, float* __restrict__ C,
                 int N, int K) {
    __shared__ float As[8][128];
    __shared__ float Bs[8][128];

    const int t  = threadIdx.x;
    const int bm = blockIdx.y * 128;
    const int bn = blockIdx.x * 128;
    const int tx = t & 15;
    const int ty = t >> 4;
    const int arow = t >> 1;          // 0..127
    const int acol = (t & 1) * 4;     // 0 or 4
    const int brow = t >> 5;          // 0..7
    const int bcol = (t & 31) * 4;    // 0..124

    const float* Ap = A + (size_t)(bm + arow) * K + acol;
    const float* Bp = B + (size_t)brow * N + bn + bcol;

    float acc[8][8];
#pragma unroll
    for (int i = 0; i < 8; i++)
#pragma unroll
        for (int j = 0; j < 8; j++) acc[i][j] = 0.f;

    for (int kt = 0; kt < K; kt += 8) {
        float4 a  = *(const float4*)(Ap + kt);
        float4 bv = *(const float4*)(Bp + (size_t)kt * N);
        As[acol + 0][arow] = a.x;
        As[acol + 1][arow] = a.y;
        As[acol + 2][arow] = a.z;
        As[acol + 3][arow] = a.w;
        *(float4*)&Bs[brow][bcol] = bv;
        __syncthreads();
#pragma unroll
        for (int k = 0; k < 8; k++) {
            float af[8], bf[8];
            *(float4*)(af)     = *(const float4*)&As[k][ty * 8];
            *(float4*)(af + 4) = *(const float4*)&As[k][ty * 8 + 4];
            *(float4*)(bf)     = *(const float4*)&Bs[k][tx * 8];
            *(float4*)(bf + 4) = *(const float4*)&Bs[k][tx * 8 + 4];
#pragma unroll
            for (int i = 0; i < 8; i++)
#pragma unroll
                for (int j = 0; j < 8; j++)
                    acc[i][j] = fmaf(af[i], bf[j], acc[i][j]);
        }
        __syncthreads();
    }

    float bvv[8];
    *(float4*)(bvv)     = *(const float4*)(bias + bn + tx * 8);
    *(float4*)(bvv + 4) = *(const float4*)(bias + bn + tx * 8 + 4);

#pragma unroll
    for (int i = 0; i < 8; i++) {
        float* crow = C + (size_t)(bm + ty * 8 + i) * N + bn + tx * 8;
#pragma unroll
        for (int jv = 0; jv < 2; jv++) {
            float vals[4];
#pragma unroll
            for (int u = 0; u < 4; u++) {
                float x = acc[i][jv * 4 + u] + bvv[jv * 4 + u];
                if (DO_GELU) x = 0.5f * x * (1.0f + erff(x * 0.70710678118654752f));
                vals[u] = x;
            }
            if (DO_ACC) {
                float4 old = *(const float4*)(crow + jv * 4);
                vals[0] += old.x; vals[1] += old.y; vals[2] += old.z; vals[3] += old.w;
            }
            float4 r = {vals[0], vals[1], vals[2], vals[3]};
            *(float4*)(crow + jv * 4) = r;
        }
    }
}

// ---------------- host orchestration ---------------------------------------
extern "C" void kernel_launch(void* const* d_in, const int* in_sizes, int n_in,
                              void* d_out, int out_size) {
    const float* emb  = (const float*)d_in[0];
    const float* w    = (const float*)d_in[1];
    const float* ln_g = (const float*)d_in[2];
    const float* ln_b = (const float*)d_in[3];
    const float* W1   = (const float*)d_in[4];
    const float* b1   = (const float*)d_in[5];
    const float* W2   = (const float*)d_in[6];
    const float* b2   = (const float*)d_in[7];
    float* out = (float*)d_out;

    float *xn, *hid, *blk;
    cudaGetSymbolAddress((void**)&xn,  g_xn);
    cudaGetSymbolAddress((void**)&hid, g_hid);
    cudaGetSymbolAddress((void**)&blk, g_blk);

    for (int l = 0; l < 16; l++) {
        int  grp        = l >> 2;
        bool hasPartial = (l & 3) != 0;

        SrcPtrs sp;
        int n = 0;
        sp.p[n++] = emb;                                               // blocks[0]
        for (int i = 0; i < grp; i++) sp.p[n++] = blk + (size_t)i * MTOK * D;  // committed
        if (hasPartial) sp.p[n++] = blk + (size_t)grp * MTOK * D;      // running partial
        for (int i = n; i < 5; i++) sp.p[i] = emb;                     // unused slots

        if (l == 15) {
            // Output is the mixed h of the last layer; its MLP is dead code.
            mix_kernel<true><<<MTOK / 8, 256>>>(sp, n, w + l * D, nullptr, nullptr, out);
        } else {
            mix_kernel<false><<<MTOK / 8, 256>>>(sp, n, w + l * D,
                                                 ln_g + l * D, ln_b + l * D, xn);
            dim3 g1(HDIM / 128, MTOK / 128);
            gemm_kernel<true, false><<<g1, 256>>>(xn, W1 + (size_t)l * D * HDIM,
                                                  b1 + (size_t)l * HDIM, hid, HDIM, D);
            dim3 g2(D / 128, MTOK / 128);
            float* dst = blk + (size_t)grp * MTOK * D;
            if (hasPartial)
                gemm_kernel<false, true><<<g2, 256>>>(hid, W2 + (size_t)l * HDIM * D,
                                                      b2 + (size_t)l * D, dst, D, HDIM);
            else
                gemm_kernel<false, false><<<g2, 256>>>(hid, W2 + (size_t)l * HDIM * D,
                                                       b2 + (size_t)l * D, dst, D, HDIM);
        }
    }
}

// round 4
// speedup vs baseline: 1.3476x; 1.3476x over previous
#include <cuda_runtime.h>
#include <cuda_bf16.h>
#include <math.h>
#include <stdint.h>

#define MTOK 65536   // 8 * 8192 tokens
#define D    128
#define HDIM 256
#define NLAYER 16
#define NTILE (MTOK / 128)   // 512 M-tiles

// ======================= device global scratch ==============================
__device__ __nv_bfloat16 g_xn_hi[(size_t)MTOK * D];
__device__ __nv_bfloat16 g_xn_lo[(size_t)MTOK * D];
__device__ __nv_bfloat16 g_hid_hi[(size_t)MTOK * HDIM];
__device__ __nv_bfloat16 g_hid_lo[(size_t)MTOK * HDIM];
__device__ float         g_blk[4][(size_t)MTOK * D];
__device__ __nv_bfloat16 g_w1t_hi[NLAYER * HDIM * D];   // [l][n=256][k=128]
__device__ __nv_bfloat16 g_w1t_lo[NLAYER * HDIM * D];
__device__ __nv_bfloat16 g_w2t_hi[NLAYER * D * HDIM];   // [l][n=128][k=256]
__device__ __nv_bfloat16 g_w2t_lo[NLAYER * D * HDIM];

// ======================= small helpers ======================================
__device__ __forceinline__ uint32_t smem_u32(const void* p) {
    uint32_t a;
    asm("{ .reg .u64 t; cvta.to.shared.u64 t, %1; cvt.u32.u64 %0, t; }" : "=r"(a) : "l"(p));
    return a;
}
__device__ __forceinline__ uint32_t pack_bf2(__nv_bfloat16 a, __nv_bfloat16 b) {
    return (uint32_t)__bfloat16_as_ushort(a) | ((uint32_t)__bfloat16_as_ushort(b) << 16);
}
__device__ __forceinline__ void ldm4(uint32_t* r, uint32_t addr) {
    asm volatile("ldmatrix.sync.aligned.m8n8.x4.shared.b16 {%0,%1,%2,%3}, [%4];"
                 : "=r"(r[0]), "=r"(r[1]), "=r"(r[2]), "=r"(r[3]) : "r"(addr));
}
__device__ __forceinline__ void mma16816(float* c, const uint32_t* a, const uint32_t* b) {
    asm volatile("mma.sync.aligned.m16n8k16.row.col.f32.bf16.bf16.f32 "
                 "{%0,%1,%2,%3}, {%4,%5,%6,%7}, {%8,%9}, {%0,%1,%2,%3};"
                 : "+f"(c[0]), "+f"(c[1]), "+f"(c[2]), "+f"(c[3])
                 : "r"(a[0]), "r"(a[1]), "r"(a[2]), "r"(a[3]), "r"(b[0]), "r"(b[1]));
}

// ======================= mma.sync GEMM ======================================
// C_block = 128(M) x 128(N). Warp tile 64x32 (2x4 warp grid). K in chunks of 128.
// 3-pass bf16 hi/lo: D = Ah*Bh + Al*Bh + Ah*Bl.
// EPI: 0 = bias+exact GELU+hi/lo bf16 split store (stride HDIM)
//      1 = bias store fp32 (stride D)     2 = bias + accumulate fp32 (stride D)
#define SROW 136                       // padded row length (bf16) -> 272B
#define TILE_B (128 * SROW * 2)        // 34816 bytes per tile
#define SMEM_BYTES (4 * TILE_B)        // 139264

template<int EPI>
__global__ __launch_bounds__(256, 1)
void mma_gemm(const __nv_bfloat16* __restrict__ A_hi, const __nv_bfloat16* __restrict__ A_lo,
              const __nv_bfloat16* __restrict__ B_hi, const __nv_bfloat16* __restrict__ B_lo,
              const float* __restrict__ bias, int K,
              __nv_bfloat16* __restrict__ O_hi, __nv_bfloat16* __restrict__ O_lo,
              float* __restrict__ Cf) {
    extern __shared__ char smem[];
    __shared__ float sbias[128];
    __nv_bfloat16* sAh = (__nv_bfloat16*)(smem);
    __nv_bfloat16* sAl = (__nv_bfloat16*)(smem + TILE_B);
    __nv_bfloat16* sBh = (__nv_bfloat16*)(smem + 2 * TILE_B);
    __nv_bfloat16* sBl = (__nv_bfloat16*)(smem + 3 * TILE_B);

    const int tid  = threadIdx.x;
    const int wid  = tid >> 5;
    const int lane = tid & 31;
    const int bn   = blockIdx.x * 128;
    const int bm   = blockIdx.y * 128;
    const int wm   = (wid & 1) * 64;          // warp m offset
    const int wn   = (wid >> 1) * 32;         // warp n offset

    if (tid < 128) sbias[tid] = bias[bn + tid];

    const uint32_t sbAh = smem_u32(sAh), sbAl = smem_u32(sAl);
    const uint32_t sbBh = smem_u32(sBh), sbBl = smem_u32(sBl);

    float acc[4][4][4];
#pragma unroll
    for (int i = 0; i < 4; i++)
#pragma unroll
        for (int j = 0; j < 4; j++)
#pragma unroll
            for (int q = 0; q < 4; q++) acc[i][j][q] = 0.f;

    // per-thread fill coords: 128 rows x 128 cols; 2 threads/row, 64 cols each
    const int frow = tid >> 1;
    const int fcol = (tid & 1) * 64;

    // ldmatrix per-lane coords
    const int a_r = (lane & 15);               // + wm + mi*16
    const int a_k = (lane >> 4) << 3;          // + k16
    const int b_r = (lane & 7) + ((lane >> 4) << 3);   // + wn + np*16
    const int b_k = ((lane >> 3) & 1) << 3;            // + k16

    for (int kc = 0; kc < K; kc += 128) {
        if (kc) __syncthreads();
        {
            const uint4* s0 = (const uint4*)(A_hi + (size_t)(bm + frow) * K + kc + fcol);
            const uint4* s1 = (const uint4*)(A_lo + (size_t)(bm + frow) * K + kc + fcol);
            const uint4* s2 = (const uint4*)(B_hi + (size_t)(bn + frow) * K + kc + fcol);
            const uint4* s3 = (const uint4*)(B_lo + (size_t)(bn + frow) * K + kc + fcol);
            uint4* d0 = (uint4*)(sAh + frow * SROW + fcol);
            uint4* d1 = (uint4*)(sAl + frow * SROW + fcol);
            uint4* d2 = (uint4*)(sBh + frow * SROW + fcol);
            uint4* d3 = (uint4*)(sBl + frow * SROW + fcol);
#pragma unroll
            for (int q = 0; q < 8; q++) { d0[q] = s0[q]; d1[q] = s1[q]; d2[q] = s2[q]; d3[q] = s3[q]; }
        }
        __syncthreads();

#pragma unroll
        for (int k16 = 0; k16 < 128; k16 += 16) {
            uint32_t ah[4][4], al[4][4], bh[4][2], bl[4][2];
#pragma unroll
            for (int mi = 0; mi < 4; mi++) {
                uint32_t off = (uint32_t)((wm + mi * 16 + a_r) * (SROW * 2) + (k16 + a_k) * 2);
                ldm4(ah[mi], sbAh + off);
                ldm4(al[mi], sbAl + off);
            }
#pragma unroll
            for (int np = 0; np < 2; np++) {
                uint32_t off = (uint32_t)((wn + np * 16 + b_r) * (SROW * 2) + (k16 + b_k) * 2);
                uint32_t t[4];
                ldm4(t, sbBh + off);
                bh[2 * np][0] = t[0]; bh[2 * np][1] = t[1];
                bh[2 * np + 1][0] = t[2]; bh[2 * np + 1][1] = t[3];
                ldm4(t, sbBl + off);
                bl[2 * np][0] = t[0]; bl[2 * np][1] = t[1];
                bl[2 * np + 1][0] = t[2]; bl[2 * np + 1][1] = t[3];
            }
#pragma unroll
            for (int mi = 0; mi < 4; mi++)
#pragma unroll
                for (int nj = 0; nj < 4; nj++) {
                    mma16816(acc[mi][nj], ah[mi], bh[nj]);
                    mma16816(acc[mi][nj], al[mi], bh[nj]);
                    mma16816(acc[mi][nj], ah[mi], bl[nj]);
                }
        }
    }

    // ---------------- epilogue ----------------
    const int g   = lane >> 2;
    const int t4  = lane & 3;
#pragma unroll
    for (int mi = 0; mi < 4; mi++) {
#pragma unroll
        for (int nj = 0; nj < 4; nj++) {
            int colL = wn + nj * 8 + 2 * t4;       // local col (0..127)
            int col  = bn + colL;                  // global col
            float b0 = sbias[colL], b1 = sbias[colL + 1];
#pragma unroll
            for (int h = 0; h < 2; h++) {
                int row = bm + wm + mi * 16 + g + h * 8;
                float x0 = acc[mi][nj][2 * h]     + b0;
                float x1 = acc[mi][nj][2 * h + 1] + b1;
                if (EPI == 0) {
                    float y0 = 0.5f * x0 * (1.0f + erff(x0 * 0.70710678118654752f));
                    float y1 = 0.5f * x1 * (1.0f + erff(x1 * 0.70710678118654752f));
                    __nv_bfloat16 h0 = __float2bfloat16(y0), h1 = __float2bfloat16(y1);
                    __nv_bfloat16 l0 = __float2bfloat16(y0 - __bfloat162float(h0));
                    __nv_bfloat16 l1 = __float2bfloat16(y1 - __bfloat162float(h1));
                    *(uint32_t*)(O_hi + (size_t)row * HDIM + col) = pack_bf2(h0, h1);
                    *(uint32_t*)(O_lo + (size_t)row * HDIM + col) = pack_bf2(l0, l1);
                } else {
                    float* cp = Cf + (size_t)row * D + col;
                    if (EPI == 2) {
                        float2 o = *(const float2*)cp;
                        x0 += o.x; x1 += o.y;
                    }
                    float2 v = {x0, x1};
                    *(float2*)cp = v;
                }
            }
        }
    }
}

// ======================= weight prep: transpose + hi/lo split ===============
__global__ void prep_weights(const float* __restrict__ W1, const float* __restrict__ W2) {
    const size_t T1 = (size_t)NLAYER * HDIM * D;
    const size_t T2 = (size_t)NLAYER * D * HDIM;
    for (size_t i = (size_t)blockIdx.x * blockDim.x + threadIdx.x; i < T1 + T2;
         i += (size_t)gridDim.x * blockDim.x) {
        float v;
        if (i < T1) {
            size_t l = i / (HDIM * D), r = i % (HDIM * D);
            size_t n = r / D, k = r % D;
            v = W1[(l * D + k) * HDIM + n];
            __nv_bfloat16 hi = __float2bfloat16(v);
            g_w1t_hi[i] = hi;
            g_w1t_lo[i] = __float2bfloat16(v - __bfloat162float(hi));
        } else {
            size_t j = i - T1;
            size_t l = j / (D * HDIM), r = j % (D * HDIM);
            size_t n = r / HDIM, k = r % HDIM;
            v = W2[(l * HDIM + k) * D + n];
            __nv_bfloat16 hi = __float2bfloat16(v);
            g_w2t_hi[j] = hi;
            g_w2t_lo[j] = __float2bfloat16(v - __bfloat162float(hi));
        }
    }
}

// ======================= mixing kernel ======================================
struct SrcPtrs { const float* p[5]; };

__device__ __forceinline__ float wsum(float v) {
#pragma unroll
    for (int o = 16; o > 0; o >>= 1) v += __shfl_xor_sync(0xffffffffu, v, o);
    return v;
}

template<bool WRITE_H>
__global__ __launch_bounds__(256)
void mix_kernel(SrcPtrs src, int n, const float* __restrict__ wrow,
                const float* __restrict__ lg, const float* __restrict__ lb,
                float* __restrict__ outp,
                __nv_bfloat16* __restrict__ out_hi, __nv_bfloat16* __restrict__ out_lo) {
    int tok  = (blockIdx.x * 256 + threadIdx.x) >> 5;
    int lane = threadIdx.x & 31;
    int base = tok * D + lane * 4;

    float4 wv = *(const float4*)(wrow + lane * 4);

    float4 v[5];
    float  lgt[5];
#pragma unroll
    for (int i = 0; i < 5; i++) {
        if (i < n) {
            float4 t = *(const float4*)(src.p[i] + base);
            v[i] = t;
            float ss = t.x*t.x + t.y*t.y + t.z*t.z + t.w*t.w;
            float dt = wv.x*t.x + wv.y*t.y + wv.z*t.z + wv.w*t.w;
            ss = wsum(ss);
            dt = wsum(dt);
            lgt[i] = dt * rsqrtf(ss * (1.0f / D) + 1e-8f);
        }
    }

    float mx = -1e30f;
#pragma unroll
    for (int i = 0; i < 5; i++) if (i < n) mx = fmaxf(mx, lgt[i]);
    float se = 0.f;
#pragma unroll
    for (int i = 0; i < 5; i++) if (i < n) { lgt[i] = expf(lgt[i] - mx); se += lgt[i]; }
    float inv = 1.f / se;

    float hx = 0.f, hy = 0.f, hz = 0.f, hw = 0.f;
#pragma unroll
    for (int i = 0; i < 5; i++) if (i < n) {
        float wt = lgt[i] * inv;
        hx += wt * v[i].x; hy += wt * v[i].y; hz += wt * v[i].z; hw += wt * v[i].w;
    }

    if (WRITE_H) {
        float4 o = {hx, hy, hz, hw};
        *(float4*)(outp + base) = o;
    } else {
        float mu = wsum(hx + hy + hz + hw) * (1.0f / D);
        float dx = hx - mu, dy = hy - mu, dz = hz - mu, dw = hw - mu;
        float var = wsum(dx*dx + dy*dy + dz*dz + dw*dw) * (1.0f / D);
        float r = rsqrtf(var + 1e-5f);
        float4 gg = *(const float4*)(lg + lane * 4);
        float4 bb = *(const float4*)(lb + lane * 4);
        float o0 = dx * r * gg.x + bb.x;
        float o1 = dy * r * gg.y + bb.y;
        float o2 = dz * r * gg.z + bb.z;
        float o3 = dw * r * gg.w + bb.w;
        __nv_bfloat16 h0 = __float2bfloat16(o0), h1 = __float2bfloat16(o1);
        __nv_bfloat16 h2 = __float2bfloat16(o2), h3 = __float2bfloat16(o3);
        uint2 uh = {pack_bf2(h0, h1), pack_bf2(h2, h3)};
        uint2 ul = {pack_bf2(__float2bfloat16(o0 - __bfloat162float(h0)),
                             __float2bfloat16(o1 - __bfloat162float(h1))),
                    pack_bf2(__float2bfloat16(o2 - __bfloat162float(h2)),
                             __float2bfloat16(o3 - __bfloat162float(h3)))};
        *(uint2*)(out_hi + base) = uh;
        *(uint2*)(out_lo + base) = ul;
    }
}

// ======================= host orchestration =================================
extern "C" void kernel_launch(void* const* d_in, const int* in_sizes, int n_in,
                              void* d_out, int out_size) {
    const float* emb  = (const float*)d_in[0];
    const float* w    = (const float*)d_in[1];
    const float* ln_g = (const float*)d_in[2];
    const float* ln_b = (const float*)d_in[3];
    const float* W1   = (const float*)d_in[4];
    const float* b1   = (const float*)d_in[5];
    const float* W2   = (const float*)d_in[6];
    const float* b2   = (const float*)d_in[7];
    float* out = (float*)d_out;

    __nv_bfloat16 *xn_hi, *xn_lo, *hid_hi, *hid_lo, *w1h, *w1l, *w2h, *w2l;
    float* blk;
    cudaGetSymbolAddress((void**)&xn_hi,  g_xn_hi);
    cudaGetSymbolAddress((void**)&xn_lo,  g_xn_lo);
    cudaGetSymbolAddress((void**)&hid_hi, g_hid_hi);
    cudaGetSymbolAddress((void**)&hid_lo, g_hid_lo);
    cudaGetSymbolAddress((void**)&blk,    g_blk);
    cudaGetSymbolAddress((void**)&w1h,    g_w1t_hi);
    cudaGetSymbolAddress((void**)&w1l,    g_w1t_lo);
    cudaGetSymbolAddress((void**)&w2h,    g_w2t_hi);
    cudaGetSymbolAddress((void**)&w2l,    g_w2t_lo);

    cudaFuncSetAttribute(mma_gemm<0>, cudaFuncAttributeMaxDynamicSharedMemorySize, SMEM_BYTES);
    cudaFuncSetAttribute(mma_gemm<1>, cudaFuncAttributeMaxDynamicSharedMemorySize, SMEM_BYTES);
    cudaFuncSetAttribute(mma_gemm<2>, cudaFuncAttributeMaxDynamicSharedMemorySize, SMEM_BYTES);

    prep_weights<<<512, 256>>>(W1, W2);

    for (int l = 0; l < NLAYER; l++) {
        int  grp        = l >> 2;
        bool hasPartial = (l & 3) != 0;

        SrcPtrs sp;
        int n = 0;
        sp.p[n++] = emb;
        for (int i = 0; i < grp; i++) sp.p[n++] = blk + (size_t)i * MTOK * D;
        if (hasPartial) sp.p[n++] = blk + (size_t)grp * MTOK * D;
        for (int i = n; i < 5; i++) sp.p[i] = emb;

        if (l == NLAYER - 1) {
            mix_kernel<true><<<MTOK / 8, 256>>>(sp, n, w + l * D, nullptr, nullptr,
                                                out, nullptr, nullptr);
        } else {
            mix_kernel<false><<<MTOK / 8, 256>>>(sp, n, w + l * D,
                                                 ln_g + l * D, ln_b + l * D,
                                                 nullptr, xn_hi, xn_lo);
            dim3 g1(2, NTILE);
            mma_gemm<0><<<g1, 256, SMEM_BYTES>>>(
                xn_hi, xn_lo,
                w1h + (size_t)l * HDIM * D, w1l + (size_t)l * HDIM * D,
                b1 + (size_t)l * HDIM, D, hid_hi, hid_lo, nullptr);
            dim3 g2(1, NTILE);
            float* dst = blk + (size_t)grp * MTOK * D;
            if (hasPartial)
                mma_gemm<2><<<g2, 256, SMEM_BYTES>>>(
                    hid_hi, hid_lo,
                    w2h + (size_t)l * D * HDIM, w2l + (size_t)l * D * HDIM,
                    b2 + (size_t)l * D, HDIM, nullptr, nullptr, dst);
            else
                mma_gemm<1><<<g2, 256, SMEM_BYTES>>>(
                    hid_hi, hid_lo,
                    w2h + (size_t)l * D * HDIM, w2l + (size_t)l * D * HDIM,
                    b2 + (size_t)l * D, HDIM, nullptr, nullptr, dst);
        }
    }
}

// round 5
// speedup vs baseline: 2.5346x; 1.8809x over previous
#include <cuda_runtime.h>
#include <cuda_fp16.h>
#include <math.h>
#include <stdint.h>

#define MTOK 65536   // 8 * 8192 tokens
#define D    128
#define HDIM 256
#define NLAYER 16

// ======================= device global scratch ==============================
__device__ __half g_xn [(size_t)MTOK * D];       // LN'd mixing output (fp16)
__device__ __half g_hid[(size_t)MTOK * HDIM];    // GELU hidden (fp16)
__device__ float  g_blk[4][(size_t)MTOK * D];    // committed blocks / partial (fp32)
__device__ __half g_w1t[NLAYER * HDIM * D];      // [l][n=256][k=128] fp16
__device__ __half g_w2t[NLAYER * D * HDIM];      // [l][n=128][k=256] fp16

// ======================= small helpers ======================================
__device__ __forceinline__ uint32_t smem_u32(const void* p) {
    uint32_t a;
    asm("{ .reg .u64 t; cvta.to.shared.u64 t, %1; cvt.u32.u64 %0, t; }" : "=r"(a) : "l"(p));
    return a;
}
__device__ __forceinline__ uint32_t pack_h2(__half a, __half b) {
    return (uint32_t)__half_as_ushort(a) | ((uint32_t)__half_as_ushort(b) << 16);
}
__device__ __forceinline__ void ldm4(uint32_t* r, uint32_t addr) {
    asm volatile("ldmatrix.sync.aligned.m8n8.x4.shared.b16 {%0,%1,%2,%3}, [%4];"
                 : "=r"(r[0]), "=r"(r[1]), "=r"(r[2]), "=r"(r[3]) : "r"(addr));
}
__device__ __forceinline__ void mma16816(float* c, const uint32_t* a, const uint32_t* b) {
    asm volatile("mma.sync.aligned.m16n8k16.row.col.f32.f16.f16.f32 "
                 "{%0,%1,%2,%3}, {%4,%5,%6,%7}, {%8,%9}, {%0,%1,%2,%3};"
                 : "+f"(c[0]), "+f"(c[1]), "+f"(c[2]), "+f"(c[3])
                 : "r"(a[0]), "r"(a[1]), "r"(a[2]), "r"(a[3]), "r"(b[0]), "r"(b[1]));
}

// ======================= fp16 mma GEMM ======================================
// CTA tile 256(M) x 128(N). 8 warps in 4x2 grid, warp tile 64x64. K chunks of 128.
// EPI: 0 = bias + exact GELU -> fp16 store (stride HDIM)
//      1 = bias -> fp32 store (stride D)    2 = bias + accumulate fp32 (stride D)
#define SROW 136                        // padded row (halves) -> 272B
#define SMEM_BYTES ((256 + 128) * SROW * 2)   // 104448

template<int EPI>
__global__ __launch_bounds__(256, 1)
void mma_gemm(const __half* __restrict__ A, const __half* __restrict__ B,
              const float* __restrict__ bias, int K,
              __half* __restrict__ Oh, float* __restrict__ Cf) {
    extern __shared__ char smem[];
    __shared__ float sbias[128];
    __half* sA = (__half*)smem;
    __half* sB = sA + 256 * SROW;

    const int tid  = threadIdx.x;
    const int wid  = tid >> 5;
    const int lane = tid & 31;
    const int bn   = blockIdx.x * 128;
    const int bm   = blockIdx.y * 256;
    const int wm   = (wid >> 1) * 64;         // 4 m-warps
    const int wn   = (wid & 1) * 64;          // 2 n-warps

    if (tid < 128) sbias[tid] = bias[bn + tid];

    const uint32_t sbA = smem_u32(sA);
    const uint32_t sbB = smem_u32(sB);

    float acc[4][8][4];
#pragma unroll
    for (int i = 0; i < 4; i++)
#pragma unroll
        for (int j = 0; j < 8; j++)
#pragma unroll
            for (int q = 0; q < 4; q++) acc[i][j][q] = 0.f;

    // ldmatrix per-lane coords (verified mapping from R4)
    const int a_r = (lane & 15);
    const int a_k = (lane >> 4) << 3;
    const int b_r = (lane & 7) + ((lane >> 4) << 3);
    const int b_k = ((lane >> 3) & 1) << 3;

    // fill coords
    const int browf = tid >> 1;
    const int bcolf = (tid & 1) * 64;

    for (int kc = 0; kc < K; kc += 128) {
        if (kc) __syncthreads();
        {   // A: 256 rows x 128 cols, one row per thread (16 uint4)
            const uint4* s = (const uint4*)(A + (size_t)(bm + tid) * K + kc);
            uint4* d = (uint4*)(sA + tid * SROW);
#pragma unroll
            for (int q = 0; q < 16; q++) d[q] = s[q];
            // B: 128 rows x 128 cols, half row per thread (8 uint4)
            const uint4* s2 = (const uint4*)(B + (size_t)(bn + browf) * K + kc + bcolf);
            uint4* d2 = (uint4*)(sB + browf * SROW + bcolf);
#pragma unroll
            for (int q = 0; q < 8; q++) d2[q] = s2[q];
        }
        __syncthreads();

#pragma unroll
        for (int k16 = 0; k16 < 128; k16 += 16) {
            uint32_t a[4][4], b[8][2];
#pragma unroll
            for (int mi = 0; mi < 4; mi++)
                ldm4(a[mi], sbA + (uint32_t)((wm + mi * 16 + a_r) * (SROW * 2) + (k16 + a_k) * 2));
#pragma unroll
            for (int np = 0; np < 4; np++) {
                uint32_t t[4];
                ldm4(t, sbB + (uint32_t)((wn + np * 16 + b_r) * (SROW * 2) + (k16 + b_k) * 2));
                b[2 * np][0] = t[0]; b[2 * np][1] = t[1];
                b[2 * np + 1][0] = t[2]; b[2 * np + 1][1] = t[3];
            }
#pragma unroll
            for (int mi = 0; mi < 4; mi++)
#pragma unroll
                for (int nj = 0; nj < 8; nj++)
                    mma16816(acc[mi][nj], a[mi], b[nj]);
        }
    }

    // ---------------- epilogue ----------------
    const int g  = lane >> 2;
    const int t4 = lane & 3;
#pragma unroll
    for (int mi = 0; mi < 4; mi++) {
#pragma unroll
        for (int nj = 0; nj < 8; nj++) {
            int colL = wn + nj * 8 + 2 * t4;
            float b0 = sbias[colL], b1 = sbias[colL + 1];
#pragma unroll
            for (int h = 0; h < 2; h++) {
                int row = bm + wm + mi * 16 + g + h * 8;
                float x0 = acc[mi][nj][2 * h]     + b0;
                float x1 = acc[mi][nj][2 * h + 1] + b1;
                if (EPI == 0) {
                    float y0 = 0.5f * x0 * (1.0f + erff(x0 * 0.70710678118654752f));
                    float y1 = 0.5f * x1 * (1.0f + erff(x1 * 0.70710678118654752f));
                    *(uint32_t*)(Oh + (size_t)row * HDIM + bn + colL) =
                        pack_h2(__float2half_rn(y0), __float2half_rn(y1));
                } else {
                    float* cp = Cf + (size_t)row * D + bn + colL;
                    if (EPI == 2) {
                        float2 o = *(const float2*)cp;
                        x0 += o.x; x1 += o.y;
                    }
                    float2 v = {x0, x1};
                    *(float2*)cp = v;
                }
            }
        }
    }
}

// ======================= weight prep: transpose + fp16 ======================
__global__ void prep_weights(const float* __restrict__ W1, const float* __restrict__ W2) {
    const size_t T1 = (size_t)NLAYER * HDIM * D;
    const size_t T2 = (size_t)NLAYER * D * HDIM;
    for (size_t i = (size_t)blockIdx.x * blockDim.x + threadIdx.x; i < T1 + T2;
         i += (size_t)gridDim.x * blockDim.x) {
        if (i < T1) {
            size_t l = i / (HDIM * D), r = i % (HDIM * D);
            size_t n = r / D, k = r % D;
            g_w1t[i] = __float2half_rn(W1[(l * D + k) * HDIM + n]);
        } else {
            size_t j = i - T1;
            size_t l = j / (D * HDIM), r = j % (D * HDIM);
            size_t n = r / HDIM, k = r % HDIM;
            g_w2t[j] = __float2half_rn(W2[(l * HDIM + k) * D + n]);
        }
    }
}

// ======================= mixing kernel ======================================
// 16 lanes per token, 8 floats per lane.
struct SrcPtrs { const float* p[5]; };

__device__ __forceinline__ float wsum16(float v) {
#pragma unroll
    for (int o = 8; o > 0; o >>= 1) v += __shfl_xor_sync(0xffffffffu, v, o);
    return v;
}

template<bool WRITE_H>
__global__ __launch_bounds__(256)
void mix_kernel(SrcPtrs src, int n, const float* __restrict__ wrow,
                const float* __restrict__ lg, const float* __restrict__ lb,
                float* __restrict__ outp, __half* __restrict__ outh) {
    int tok  = blockIdx.x * 16 + (threadIdx.x >> 4);
    int l16  = threadIdx.x & 15;
    int base = tok * D + l16 * 8;

    float4 w0 = *(const float4*)(wrow + l16 * 8);
    float4 w1 = *(const float4*)(wrow + l16 * 8 + 4);

    float v[5][8];
    float lgt[5];
#pragma unroll
    for (int i = 0; i < 5; i++) {
        if (i < n) {
            float4 t0 = *(const float4*)(src.p[i] + base);
            float4 t1 = *(const float4*)(src.p[i] + base + 4);
            v[i][0] = t0.x; v[i][1] = t0.y; v[i][2] = t0.z; v[i][3] = t0.w;
            v[i][4] = t1.x; v[i][5] = t1.y; v[i][6] = t1.z; v[i][7] = t1.w;
            float ss = t0.x*t0.x + t0.y*t0.y + t0.z*t0.z + t0.w*t0.w
                     + t1.x*t1.x + t1.y*t1.y + t1.z*t1.z + t1.w*t1.w;
            float dt = w0.x*t0.x + w0.y*t0.y + w0.z*t0.z + w0.w*t0.w
                     + w1.x*t1.x + w1.y*t1.y + w1.z*t1.z + w1.w*t1.w;
            ss = wsum16(ss);
            dt = wsum16(dt);
            lgt[i] = dt * rsqrtf(ss * (1.0f / D) + 1e-8f);
        }
    }

    float mx = -1e30f;
#pragma unroll
    for (int i = 0; i < 5; i++) if (i < n) mx = fmaxf(mx, lgt[i]);
    float se = 0.f;
#pragma unroll
    for (int i = 0; i < 5; i++) if (i < n) { lgt[i] = expf(lgt[i] - mx); se += lgt[i]; }
    float inv = 1.f / se;

    float h[8];
#pragma unroll
    for (int j = 0; j < 8; j++) h[j] = 0.f;
#pragma unroll
    for (int i = 0; i < 5; i++) if (i < n) {
        float wt = lgt[i] * inv;
#pragma unroll
        for (int j = 0; j < 8; j++) h[j] += wt * v[i][j];
    }

    if (WRITE_H) {
        float4 o0 = {h[0], h[1], h[2], h[3]};
        float4 o1 = {h[4], h[5], h[6], h[7]};
        *(float4*)(outp + base) = o0;
        *(float4*)(outp + base + 4) = o1;
    } else {
        float s = 0.f;
#pragma unroll
        for (int j = 0; j < 8; j++) s += h[j];
        float mu = wsum16(s) * (1.0f / D);
        float vs = 0.f;
#pragma unroll
        for (int j = 0; j < 8; j++) { float d = h[j] - mu; vs += d * d; }
        float var = wsum16(vs) * (1.0f / D);
        float r = rsqrtf(var + 1e-5f);
        float4 g0 = *(const float4*)(lg + l16 * 8);
        float4 g1 = *(const float4*)(lg + l16 * 8 + 4);
        float4 b0 = *(const float4*)(lb + l16 * 8);
        float4 b1 = *(const float4*)(lb + l16 * 8 + 4);
        float gg[8] = {g0.x, g0.y, g0.z, g0.w, g1.x, g1.y, g1.z, g1.w};
        float bb[8] = {b0.x, b0.y, b0.z, b0.w, b1.x, b1.y, b1.z, b1.w};
        uint32_t pk[4];
#pragma unroll
        for (int q = 0; q < 4; q++) {
            float o0 = (h[2*q]   - mu) * r * gg[2*q]   + bb[2*q];
            float o1 = (h[2*q+1] - mu) * r * gg[2*q+1] + bb[2*q+1];
            pk[q] = pack_h2(__float2half_rn(o0), __float2half_rn(o1));
        }
        // wait: need 8 outputs -> indices 0..7 map to pairs (0,1)..(6,7)
        *(uint2*)(outh + base)     = make_uint2(pk[0], pk[1]);
        *(uint2*)(outh + base + 4) = make_uint2(pk[2], pk[3]);
    }
}

// ======================= host orchestration =================================
extern "C" void kernel_launch(void* const* d_in, const int* in_sizes, int n_in,
                              void* d_out, int out_size) {
    const float* emb  = (const float*)d_in[0];
    const float* w    = (const float*)d_in[1];
    const float* ln_g = (const float*)d_in[2];
    const float* ln_b = (const float*)d_in[3];
    const float* W1   = (const float*)d_in[4];
    const float* b1   = (const float*)d_in[5];
    const float* W2   = (const float*)d_in[6];
    const float* b2   = (const float*)d_in[7];
    float* out = (float*)d_out;

    __half *xn, *hid, *w1t, *w2t;
    float* blk;
    cudaGetSymbolAddress((void**)&xn,  g_xn);
    cudaGetSymbolAddress((void**)&hid, g_hid);
    cudaGetSymbolAddress((void**)&blk, g_blk);
    cudaGetSymbolAddress((void**)&w1t, g_w1t);
    cudaGetSymbolAddress((void**)&w2t, g_w2t);

    cudaFuncSetAttribute(mma_gemm<0>, cudaFuncAttributeMaxDynamicSharedMemorySize, SMEM_BYTES);
    cudaFuncSetAttribute(mma_gemm<1>, cudaFuncAttributeMaxDynamicSharedMemorySize, SMEM_BYTES);
    cudaFuncSetAttribute(mma_gemm<2>, cudaFuncAttributeMaxDynamicSharedMemorySize, SMEM_BYTES);

    prep_weights<<<512, 256>>>(W1, W2);

    for (int l = 0; l < NLAYER; l++) {
        int  grp        = l >> 2;
        bool hasPartial = (l & 3) != 0;

        SrcPtrs sp;
        int n = 0;
        sp.p[n++] = emb;
        for (int i = 0; i < grp; i++) sp.p[n++] = blk + (size_t)i * MTOK * D;
        if (hasPartial) sp.p[n++] = blk + (size_t)grp * MTOK * D;
        for (int i = n; i < 5; i++) sp.p[i] = emb;

        if (l == NLAYER - 1) {
            mix_kernel<true><<<MTOK / 16, 256>>>(sp, n, w + l * D, nullptr, nullptr,
                                                 out, nullptr);
        } else {
            mix_kernel<false><<<MTOK / 16, 256>>>(sp, n, w + l * D,
                                                  ln_g + l * D, ln_b + l * D,
                                                  nullptr, xn);
            dim3 g1(2, MTOK / 256);
            mma_gemm<0><<<g1, 256, SMEM_BYTES>>>(
                xn, w1t + (size_t)l * HDIM * D, b1 + (size_t)l * HDIM, D, hid, nullptr);
            dim3 g2(1, MTOK / 256);
            float* dst = blk + (size_t)grp * MTOK * D;
            if (hasPartial)
                mma_gemm<2><<<g2, 256, SMEM_BYTES>>>(
                    hid, w2t + (size_t)l * D * HDIM, b2 + (size_t)l * D, HDIM, nullptr, dst);
            else
                mma_gemm<1><<<g2, 256, SMEM_BYTES>>>(
                    hid, w2t + (size_t)l * D * HDIM, b2 + (size_t)l * D, HDIM, nullptr, dst);
        }
    }
}

// round 6
// speedup vs baseline: 2.7626x; 1.0899x over previous
#include <cuda_runtime.h>
#include <cuda_fp16.h>
#include <math.h>
#include <stdint.h>

#define MTOK 65536   // 8 * 8192 tokens
#define D    128
#define HDIM 256
#define NLAYER 16

// ======================= device global scratch ==============================
__device__ __half g_xn [(size_t)MTOK * D];       // LN'd mixing output (fp16)
__device__ __half g_hid[(size_t)MTOK * HDIM];    // GELU hidden (fp16)
__device__ float  g_blk[4][(size_t)MTOK * D];    // committed blocks / partial (fp32)
__device__ __half g_w1t[NLAYER * HDIM * D];      // [l][n=256][k=128] fp16
__device__ __half g_w2t[NLAYER * D * HDIM];      // [l][n=128][k=256] fp16

// ======================= small helpers ======================================
__device__ __forceinline__ uint32_t smem_u32(const void* p) {
    uint32_t a;
    asm("{ .reg .u64 t; cvta.to.shared.u64 t, %1; cvt.u32.u64 %0, t; }" : "=r"(a) : "l"(p));
    return a;
}
__device__ __forceinline__ uint32_t pack_h2(__half a, __half b) {
    return (uint32_t)__half_as_ushort(a) | ((uint32_t)__half_as_ushort(b) << 16);
}
__device__ __forceinline__ void ldm4(uint32_t* r, uint32_t addr) {
    asm volatile("ldmatrix.sync.aligned.m8n8.x4.shared.b16 {%0,%1,%2,%3}, [%4];"
                 : "=r"(r[0]), "=r"(r[1]), "=r"(r[2]), "=r"(r[3]) : "r"(addr));
}
__device__ __forceinline__ void mma16816(float* c, const uint32_t* a, const uint32_t* b) {
    asm volatile("mma.sync.aligned.m16n8k16.row.col.f32.f16.f16.f32 "
                 "{%0,%1,%2,%3}, {%4,%5,%6,%7}, {%8,%9}, {%0,%1,%2,%3};"
                 : "+f"(c[0]), "+f"(c[1]), "+f"(c[2]), "+f"(c[3])
                 : "r"(a[0]), "r"(a[1]), "r"(a[2]), "r"(a[3]), "r"(b[0]), "r"(b[1]));
}
__device__ __forceinline__ void cp16(uint32_t dst, const void* src) {
    asm volatile("cp.async.cg.shared.global [%0], [%1], 16;" :: "r"(dst), "l"(src));
}
#define CP_COMMIT() asm volatile("cp.async.commit_group;" ::: "memory")
#define CP_WAIT0()  asm volatile("cp.async.wait_group 0;"  ::: "memory")

// ======================= fp16 mma GEMM ======================================
// CTA tile 128(M) x 128(N). 8 warps in 4x2 grid, warp tile 32x64.
// B (128 rows x K cols) fully resident; A chunked at K=128. cp.async fills.
// EPI: 0 = bias + exact GELU -> fp16 store (stride HDIM)
//      1 = bias -> fp32 store (stride D)    2 = bias + accumulate fp32 (stride D)
#define SROWA 136                         // A padded row (halves) -> 272B

template<int EPI, int K>
__global__ __launch_bounds__(256, 2)
void mma_gemm(const __half* __restrict__ A, const __half* __restrict__ B,
              const float* __restrict__ bias,
              __half* __restrict__ Oh, float* __restrict__ Cf) {
    constexpr int SROWB = (K == 128) ? 136 : 264;    // B padded row (halves)
    extern __shared__ char smem[];
    __shared__ float sbias[128];
    __half* sA = (__half*)smem;                      // 128*136*2 = 34816 B
    __half* sB = sA + 128 * SROWA;                   // 128*SROWB*2 B

    const int tid  = threadIdx.x;
    const int wid  = tid >> 5;
    const int lane = tid & 31;
    const int bn   = blockIdx.x * 128;
    const int bm   = blockIdx.y * 128;
    const int wm   = (wid >> 1) * 32;     // 4 m-warps
    const int wn   = (wid & 1) * 64;      // 2 n-warps

    const uint32_t sbA = smem_u32(sA);
    const uint32_t sbB = smem_u32(sB);

    const int frow = tid >> 1;            // fill row 0..127

    // ---- prologue fill: all of B, A chunk 0, bias ----
    {
        if (K == 128) {
            int col = (tid & 1) * 64;
            const char* src = (const char*)(B + (size_t)(bn + frow) * K + col);
            uint32_t dst = sbB + (uint32_t)(frow * SROWB + col) * 2;
#pragma unroll
            for (int q = 0; q < 8; q++) cp16(dst + q * 16, src + q * 16);
        } else {
            int col = (tid & 1) * 128;
            const char* src = (const char*)(B + (size_t)(bn + frow) * K + col);
            uint32_t dst = sbB + (uint32_t)(frow * SROWB + col) * 2;
#pragma unroll
            for (int q = 0; q < 16; q++) cp16(dst + q * 16, src + q * 16);
        }
        {
            int col = (tid & 1) * 64;
            const char* src = (const char*)(A + (size_t)(bm + frow) * K + col);
            uint32_t dst = sbA + (uint32_t)(frow * SROWA + col) * 2;
#pragma unroll
            for (int q = 0; q < 8; q++) cp16(dst + q * 16, src + q * 16);
        }
        if (tid < 128) sbias[tid] = bias[bn + tid];
        CP_COMMIT();
    }

    float acc[2][8][4];
#pragma unroll
    for (int i = 0; i < 2; i++)
#pragma unroll
        for (int j = 0; j < 8; j++)
#pragma unroll
            for (int q = 0; q < 4; q++) acc[i][j][q] = 0.f;

    // ldmatrix per-lane coords
    const int a_r = (lane & 15);
    const int a_k = (lane >> 4) << 3;
    const int b_r = (lane & 7) + ((lane >> 4) << 3);
    const int b_k = ((lane >> 3) & 1) << 3;

    CP_WAIT0();
    __syncthreads();

#pragma unroll
    for (int kc = 0; kc < K; kc += 128) {
        if (kc) {   // reload A chunk (B stays resident)
            __syncthreads();
            int col = (tid & 1) * 64;
            const char* src = (const char*)(A + (size_t)(bm + frow) * K + kc + col);
            uint32_t dst = sbA + (uint32_t)(frow * SROWA + col) * 2;
#pragma unroll
            for (int q = 0; q < 8; q++) cp16(dst + q * 16, src + q * 16);
            CP_COMMIT();
            CP_WAIT0();
            __syncthreads();
        }
#pragma unroll
        for (int k16 = 0; k16 < 128; k16 += 16) {
            uint32_t a[2][4], b[8][2];
#pragma unroll
            for (int mi = 0; mi < 2; mi++)
                ldm4(a[mi], sbA + (uint32_t)((wm + mi * 16 + a_r) * (SROWA * 2) + (k16 + a_k) * 2));
#pragma unroll
            for (int np = 0; np < 4; np++) {
                uint32_t t[4];
                ldm4(t, sbB + (uint32_t)((wn + np * 16 + b_r) * (SROWB * 2) + (kc + k16 + b_k) * 2));
                b[2 * np][0] = t[0]; b[2 * np][1] = t[1];
                b[2 * np + 1][0] = t[2]; b[2 * np + 1][1] = t[3];
            }
#pragma unroll
            for (int mi = 0; mi < 2; mi++)
#pragma unroll
                for (int nj = 0; nj < 8; nj++)
                    mma16816(acc[mi][nj], a[mi], b[nj]);
        }
    }

    // ---------------- epilogue ----------------
    const int g  = lane >> 2;
    const int t4 = lane & 3;
#pragma unroll
    for (int mi = 0; mi < 2; mi++) {
#pragma unroll
        for (int nj = 0; nj < 8; nj++) {
            int colL = wn + nj * 8 + 2 * t4;
            float b0 = sbias[colL], b1 = sbias[colL + 1];
#pragma unroll
            for (int h = 0; h < 2; h++) {
                int row = bm + wm + mi * 16 + g + h * 8;
                float x0 = acc[mi][nj][2 * h]     + b0;
                float x1 = acc[mi][nj][2 * h + 1] + b1;
                if (EPI == 0) {
                    float y0 = 0.5f * x0 * (1.0f + erff(x0 * 0.70710678118654752f));
                    float y1 = 0.5f * x1 * (1.0f + erff(x1 * 0.70710678118654752f));
                    *(uint32_t*)(Oh + (size_t)row * HDIM + bn + colL) =
                        pack_h2(__float2half_rn(y0), __float2half_rn(y1));
                } else {
                    float* cp = Cf + (size_t)row * D + bn + colL;
                    if (EPI == 2) {
                        float2 o = *(const float2*)cp;
                        x0 += o.x; x1 += o.y;
                    }
                    float2 v = {x0, x1};
                    *(float2*)cp = v;
                }
            }
        }
    }
}

// ======================= weight prep: transpose + fp16 ======================
__global__ void prep_weights(const float* __restrict__ W1, const float* __restrict__ W2) {
    const size_t T1 = (size_t)NLAYER * HDIM * D;
    const size_t T2 = (size_t)NLAYER * D * HDIM;
    for (size_t i = (size_t)blockIdx.x * blockDim.x + threadIdx.x; i < T1 + T2;
         i += (size_t)gridDim.x * blockDim.x) {
        if (i < T1) {
            size_t l = i / (HDIM * D), r = i % (HDIM * D);
            size_t n = r / D, k = r % D;
            g_w1t[i] = __float2half_rn(W1[(l * D + k) * HDIM + n]);
        } else {
            size_t j = i - T1;
            size_t l = j / (D * HDIM), r = j % (D * HDIM);
            size_t n = r / HDIM, k = r % HDIM;
            g_w2t[j] = __float2half_rn(W2[(l * HDIM + k) * D + n]);
        }
    }
}

// ======================= mixing kernel ======================================
// 16 lanes per token, 8 floats per lane.
struct SrcPtrs { const float* p[5]; };

__device__ __forceinline__ float wsum16(float v) {
#pragma unroll
    for (int o = 8; o > 0; o >>= 1) v += __shfl_xor_sync(0xffffffffu, v, o);
    return v;
}

template<bool WRITE_H>
__global__ __launch_bounds__(256)
void mix_kernel(SrcPtrs src, int n, const float* __restrict__ wrow,
                const float* __restrict__ lg, const float* __restrict__ lb,
                float* __restrict__ outp, __half* __restrict__ outh) {
    int tok  = blockIdx.x * 16 + (threadIdx.x >> 4);
    int l16  = threadIdx.x & 15;
    int base = tok * D + l16 * 8;

    float4 w0 = *(const float4*)(wrow + l16 * 8);
    float4 w1 = *(const float4*)(wrow + l16 * 8 + 4);

    float v[5][8];
    float lgt[5];
#pragma unroll
    for (int i = 0; i < 5; i++) {
        if (i < n) {
            float4 t0 = *(const float4*)(src.p[i] + base);
            float4 t1 = *(const float4*)(src.p[i] + base + 4);
            v[i][0] = t0.x; v[i][1] = t0.y; v[i][2] = t0.z; v[i][3] = t0.w;
            v[i][4] = t1.x; v[i][5] = t1.y; v[i][6] = t1.z; v[i][7] = t1.w;
            float ss = t0.x*t0.x + t0.y*t0.y + t0.z*t0.z + t0.w*t0.w
                     + t1.x*t1.x + t1.y*t1.y + t1.z*t1.z + t1.w*t1.w;
            float dt = w0.x*t0.x + w0.y*t0.y + w0.z*t0.z + w0.w*t0.w
                     + w1.x*t1.x + w1.y*t1.y + w1.z*t1.z + w1.w*t1.w;
            ss = wsum16(ss);
            dt = wsum16(dt);
            lgt[i] = dt * rsqrtf(ss * (1.0f / D) + 1e-8f);
        }
    }

    float mx = -1e30f;
#pragma unroll
    for (int i = 0; i < 5; i++) if (i < n) mx = fmaxf(mx, lgt[i]);
    float se = 0.f;
#pragma unroll
    for (int i = 0; i < 5; i++) if (i < n) { lgt[i] = expf(lgt[i] - mx); se += lgt[i]; }
    float inv = 1.f / se;

    float h[8];
#pragma unroll
    for (int j = 0; j < 8; j++) h[j] = 0.f;
#pragma unroll
    for (int i = 0; i < 5; i++) if (i < n) {
        float wt = lgt[i] * inv;
#pragma unroll
        for (int j = 0; j < 8; j++) h[j] += wt * v[i][j];
    }

    if (WRITE_H) {
        float4 o0 = {h[0], h[1], h[2], h[3]};
        float4 o1 = {h[4], h[5], h[6], h[7]};
        *(float4*)(outp + base) = o0;
        *(float4*)(outp + base + 4) = o1;
    } else {
        float s = 0.f;
#pragma unroll
        for (int j = 0; j < 8; j++) s += h[j];
        float mu = wsum16(s) * (1.0f / D);
        float vs = 0.f;
#pragma unroll
        for (int j = 0; j < 8; j++) { float d = h[j] - mu; vs += d * d; }
        float var = wsum16(vs) * (1.0f / D);
        float r = rsqrtf(var + 1e-5f);
        float4 g0 = *(const float4*)(lg + l16 * 8);
        float4 g1 = *(const float4*)(lg + l16 * 8 + 4);
        float4 b0 = *(const float4*)(lb + l16 * 8);
        float4 b1 = *(const float4*)(lb + l16 * 8 + 4);
        float gg[8] = {g0.x, g0.y, g0.z, g0.w, g1.x, g1.y, g1.z, g1.w};
        float bb[8] = {b0.x, b0.y, b0.z, b0.w, b1.x, b1.y, b1.z, b1.w};
        uint32_t pk[4];
#pragma unroll
        for (int q = 0; q < 4; q++) {
            float o0 = (h[2*q]   - mu) * r * gg[2*q]   + bb[2*q];
            float o1 = (h[2*q+1] - mu) * r * gg[2*q+1] + bb[2*q+1];
            pk[q] = pack_h2(__float2half_rn(o0), __float2half_rn(o1));
        }
        *(uint2*)(outh + base)     = make_uint2(pk[0], pk[1]);
        *(uint2*)(outh + base + 4) = make_uint2(pk[2], pk[3]);
    }
}

// ======================= host orchestration =================================
#define SMEM1 (128 * SROWA * 2 + 128 * 136 * 2)   // 69632
#define SMEM2 (128 * SROWA * 2 + 128 * 264 * 2)   // 102400

extern "C" void kernel_launch(void* const* d_in, const int* in_sizes, int n_in,
                              void* d_out, int out_size) {
    const float* emb  = (const float*)d_in[0];
    const float* w    = (const float*)d_in[1];
    const float* ln_g = (const float*)d_in[2];
    const float* ln_b = (const float*)d_in[3];
    const float* W1   = (const float*)d_in[4];
    const float* b1   = (const float*)d_in[5];
    const float* W2   = (const float*)d_in[6];
    const float* b2   = (const float*)d_in[7];
    float* out = (float*)d_out;

    __half *xn, *hid, *w1t, *w2t;
    float* blk;
    cudaGetSymbolAddress((void**)&xn,  g_xn);
    cudaGetSymbolAddress((void**)&hid, g_hid);
    cudaGetSymbolAddress((void**)&blk, g_blk);
    cudaGetSymbolAddress((void**)&w1t, g_w1t);
    cudaGetSymbolAddress((void**)&w2t, g_w2t);

    cudaFuncSetAttribute(mma_gemm<0,128>, cudaFuncAttributeMaxDynamicSharedMemorySize, SMEM1);
    cudaFuncSetAttribute(mma_gemm<1,256>, cudaFuncAttributeMaxDynamicSharedMemorySize, SMEM2);
    cudaFuncSetAttribute(mma_gemm<2,256>, cudaFuncAttributeMaxDynamicSharedMemorySize, SMEM2);

    prep_weights<<<512, 256>>>(W1, W2);

    for (int l = 0; l < NLAYER; l++) {
        int  grp        = l >> 2;
        bool hasPartial = (l & 3) != 0;

        SrcPtrs sp;
        int n = 0;
        sp.p[n++] = emb;
        for (int i = 0; i < grp; i++) sp.p[n++] = blk + (size_t)i * MTOK * D;
        if (hasPartial) sp.p[n++] = blk + (size_t)grp * MTOK * D;
        for (int i = n; i < 5; i++) sp.p[i] = emb;

        if (l == NLAYER - 1) {
            mix_kernel<true><<<MTOK / 16, 256>>>(sp, n, w + l * D, nullptr, nullptr,
                                                 out, nullptr);
        } else {
            mix_kernel<false><<<MTOK / 16, 256>>>(sp, n, w + l * D,
                                                  ln_g + l * D, ln_b + l * D,
                                                  nullptr, xn);
            dim3 g1(2, MTOK / 128);
            mma_gemm<0,128><<<g1, 256, SMEM1>>>(
                xn, w1t + (size_t)l * HDIM * D, b1 + (size_t)l * HDIM, hid, nullptr);
            dim3 g2(1, MTOK / 128);
            float* dst = blk + (size_t)grp * MTOK * D;
            if (hasPartial)
                mma_gemm<2,256><<<g2, 256, SMEM2>>>(
                    hid, w2t + (size_t)l * D * HDIM, b2 + (size_t)l * D, nullptr, dst);
            else
                mma_gemm<1,256><<<g2, 256, SMEM2>>>(
                    hid, w2t + (size_t)l * D * HDIM, b2 + (size_t)l * D, nullptr, dst);
        }
    }
}